// round 1
// baseline (speedup 1.0000x reference)
#include <cuda_runtime.h>
#include <math.h>

#define BB 128
#define TT 512
#define VV 128
#define EE 256
#define HH 1024
#define FH 4096   // 4*H

// ---------------- static device scratch (allocation-free) ----------------
__device__ float g_embW[VV * FH];                 // emb@W + b  (2 MB)
__device__ float g_h[2][BB * HH];                 // double-buffered hidden state
__device__ float g_c[BB * HH];                    // cell state
__device__ float g_states[(size_t)BB * TT * HH];  // all h_t (256 MB)

// ---------------- init: zero h[0] and c ----------------
__global__ void zero_hc_kernel() {
    int i = blockIdx.x * blockDim.x + threadIdx.x;  // 131072 total
    g_h[0][i] = 0.0f;
    g_c[i]    = 0.0f;
}

// ---------------- embW = emb @ W + b  (V=128 rows only) ----------------
__global__ void embw_kernel(const float* __restrict__ emb,
                            const float* __restrict__ W,
                            const float* __restrict__ b) {
    __shared__ float se[EE];
    int v   = blockIdx.y;
    int col = blockIdx.x * blockDim.x + threadIdx.x;  // 0..4095
    se[threadIdx.x] = emb[v * EE + threadIdx.x];      // blockDim == 256 == EE
    __syncthreads();
    float acc = b[col];
#pragma unroll 8
    for (int k = 0; k < EE; k++)
        acc = fmaf(se[k], W[k * FH + col], acc);
    g_embW[v * FH + col] = acc;
}

// ---------------- one LSTM step: z = embW[tok] + h@U, gates, mask ----------------
// Grid: 128 CTAs, each owns 8 hidden units j (all 4 gates) x all 128 batch rows.
// Threads: 256.  tx = j within tile (0..7), ty = batch group (0..31), 4 rows each.
__global__ void __launch_bounds__(256) step_kernel(const int* __restrict__ tokens,
                                                   const float* __restrict__ U,
                                                   int t) {
    __shared__ float As[128][17];   // h tile [m][k], padded
    __shared__ float Bs[16][32];    // U tile [k][nn], nn = jj*4 + gate

    const float* __restrict__ h_in  = g_h[t & 1];
    float* __restrict__       h_out = g_h[(t + 1) & 1];

    const int tid = threadIdx.x;
    const int tx  = tid & 7;    // jj
    const int ty  = tid >> 3;   // m-group
    const int j0  = blockIdx.x * 8;

    float acc[4][4];
#pragma unroll
    for (int i = 0; i < 4; i++)
#pragma unroll
        for (int jn = 0; jn < 4; jn++) acc[i][jn] = 0.0f;

    for (int k0 = 0; k0 < HH; k0 += 16) {
        // load h tile: 128 x 16
#pragma unroll
        for (int r = 0; r < 8; r++) {
            int idx = tid + r * 256;
            int m = idx >> 4, k = idx & 15;
            As[m][k] = h_in[m * HH + k0 + k];
        }
        // load U tile: 16 x 32 (8 j-cols x 4 gates, gate stride H)
#pragma unroll
        for (int r = 0; r < 2; r++) {
            int idx = tid + r * 256;
            int k = idx >> 5, nn = idx & 31;
            int jj = nn >> 2, g = nn & 3;
            Bs[k][nn] = U[(k0 + k) * FH + g * HH + j0 + jj];
        }
        __syncthreads();
#pragma unroll
        for (int kk = 0; kk < 16; kk++) {
            float4 b4 = *reinterpret_cast<const float4*>(&Bs[kk][tx * 4]);
            float a0 = As[ty * 4 + 0][kk];
            float a1 = As[ty * 4 + 1][kk];
            float a2 = As[ty * 4 + 2][kk];
            float a3 = As[ty * 4 + 3][kk];
            acc[0][0] = fmaf(a0, b4.x, acc[0][0]);
            acc[0][1] = fmaf(a0, b4.y, acc[0][1]);
            acc[0][2] = fmaf(a0, b4.z, acc[0][2]);
            acc[0][3] = fmaf(a0, b4.w, acc[0][3]);
            acc[1][0] = fmaf(a1, b4.x, acc[1][0]);
            acc[1][1] = fmaf(a1, b4.y, acc[1][1]);
            acc[1][2] = fmaf(a1, b4.z, acc[1][2]);
            acc[1][3] = fmaf(a1, b4.w, acc[1][3]);
            acc[2][0] = fmaf(a2, b4.x, acc[2][0]);
            acc[2][1] = fmaf(a2, b4.y, acc[2][1]);
            acc[2][2] = fmaf(a2, b4.z, acc[2][2]);
            acc[2][3] = fmaf(a2, b4.w, acc[2][3]);
            acc[3][0] = fmaf(a3, b4.x, acc[3][0]);
            acc[3][1] = fmaf(a3, b4.y, acc[3][1]);
            acc[3][2] = fmaf(a3, b4.z, acc[3][2]);
            acc[3][3] = fmaf(a3, b4.w, acc[3][3]);
        }
        __syncthreads();
    }

    // fused gate epilogue
    const int j = j0 + tx;
#pragma unroll
    for (int im = 0; im < 4; im++) {
        int m   = ty * 4 + im;
        int tok = tokens[m * TT + t];
        const float* ew = &g_embW[tok * FH + j];
        float zi = acc[im][0] + ew[0];
        float zf = acc[im][1] + ew[HH];
        float zg = acc[im][2] + ew[2 * HH];
        float zo = acc[im][3] + ew[3 * HH];
        float ig = 1.0f / (1.0f + expf(-zi));
        float fg = 1.0f / (1.0f + expf(-zf));
        float gg = tanhf(zg);
        float og = 1.0f / (1.0f + expf(-zo));
        float cp = g_c[m * HH + j];
        float cn = fg * cp + ig * gg;
        float hn = og * tanhf(cn);
        float hp = h_in[m * HH + j];
        bool  mk = (tok != 0);
        float ho = mk ? hn : hp;
        float co = mk ? cn : cp;
        g_c[m * HH + j]   = co;
        h_out[m * HH + j] = ho;
        g_states[((size_t)m * TT + t) * HH + j] = ho;
    }
}

// ---------------- logits = states @ Wd + bd (written to d_out) ----------------
__global__ void __launch_bounds__(256) logits_kernel(const float* __restrict__ Wd,
                                                     const float* __restrict__ bd,
                                                     float* __restrict__ out) {
    __shared__ float Ss[32][33];    // states tile [row][k]
    __shared__ float Ws[32][128];   // Wd tile [k][v]

    const int tid = threadIdx.x;
    const int tx  = tid & 31;   // v-group: v = tx*4
    const int ty  = tid >> 5;   // row-group: row = ty*4
    const size_t row0 = (size_t)blockIdx.x * 32;

    float acc[4][4];
#pragma unroll
    for (int i = 0; i < 4; i++)
#pragma unroll
        for (int jn = 0; jn < 4; jn++) acc[i][jn] = 0.0f;

    for (int k0 = 0; k0 < HH; k0 += 32) {
#pragma unroll
        for (int r = 0; r < 4; r++) {
            int idx = tid + r * 256;
            int rr = idx >> 5, kk = idx & 31;
            Ss[rr][kk] = g_states[(row0 + rr) * HH + k0 + kk];
        }
#pragma unroll
        for (int r = 0; r < 16; r++) {
            int idx = tid + r * 256;
            int kk = idx >> 7, v = idx & 127;
            Ws[kk][v] = Wd[(k0 + kk) * VV + v];
        }
        __syncthreads();
#pragma unroll
        for (int kk = 0; kk < 32; kk++) {
            float4 b4 = *reinterpret_cast<const float4*>(&Ws[kk][tx * 4]);
            float a0 = Ss[ty * 4 + 0][kk];
            float a1 = Ss[ty * 4 + 1][kk];
            float a2 = Ss[ty * 4 + 2][kk];
            float a3 = Ss[ty * 4 + 3][kk];
            acc[0][0] = fmaf(a0, b4.x, acc[0][0]);
            acc[0][1] = fmaf(a0, b4.y, acc[0][1]);
            acc[0][2] = fmaf(a0, b4.z, acc[0][2]);
            acc[0][3] = fmaf(a0, b4.w, acc[0][3]);
            acc[1][0] = fmaf(a1, b4.x, acc[1][0]);
            acc[1][1] = fmaf(a1, b4.y, acc[1][1]);
            acc[1][2] = fmaf(a1, b4.z, acc[1][2]);
            acc[1][3] = fmaf(a1, b4.w, acc[1][3]);
            acc[2][0] = fmaf(a2, b4.x, acc[2][0]);
            acc[2][1] = fmaf(a2, b4.y, acc[2][1]);
            acc[2][2] = fmaf(a2, b4.z, acc[2][2]);
            acc[2][3] = fmaf(a2, b4.w, acc[2][3]);
            acc[3][0] = fmaf(a3, b4.x, acc[3][0]);
            acc[3][1] = fmaf(a3, b4.y, acc[3][1]);
            acc[3][2] = fmaf(a3, b4.z, acc[3][2]);
            acc[3][3] = fmaf(a3, b4.w, acc[3][3]);
        }
        __syncthreads();
    }

#pragma unroll
    for (int im = 0; im < 4; im++) {
#pragma unroll
        for (int iv = 0; iv < 4; iv++) {
            int v = tx * 4 + iv;
            out[(row0 + ty * 4 + im) * VV + v] = acc[im][iv] + bd[v];
        }
    }
}

// ---------------- row softmax over V=128, in place on d_out ----------------
__global__ void softmax_kernel(float* __restrict__ out) {
    __shared__ float red[4];
    const size_t row = blockIdx.x;
    const int v    = threadIdx.x;     // 128 threads
    const int lane = v & 31;
    const int wid  = v >> 5;

    float x = out[row * VV + v];

    float m = x;
#pragma unroll
    for (int o = 16; o > 0; o >>= 1)
        m = fmaxf(m, __shfl_xor_sync(0xFFFFFFFFu, m, o));
    if (lane == 0) red[wid] = m;
    __syncthreads();
    m = fmaxf(fmaxf(red[0], red[1]), fmaxf(red[2], red[3]));
    __syncthreads();

    float e = expf(x - m);
    float s = e;
#pragma unroll
    for (int o = 16; o > 0; o >>= 1)
        s += __shfl_xor_sync(0xFFFFFFFFu, s, o);
    if (lane == 0) red[wid] = s;
    __syncthreads();
    s = red[0] + red[1] + red[2] + red[3];

    out[row * VV + v] = e / s;
}

// ---------------- launch ----------------
extern "C" void kernel_launch(void* const* d_in, const int* in_sizes, int n_in,
                              void* d_out, int out_size) {
    const int*   tokens = (const int*)  d_in[0];
    const float* emb    = (const float*)d_in[1];
    const float* W      = (const float*)d_in[2];
    const float* U      = (const float*)d_in[3];
    const float* b      = (const float*)d_in[4];
    const float* Wd     = (const float*)d_in[5];
    const float* bd     = (const float*)d_in[6];
    float* out = (float*)d_out;

    zero_hc_kernel<<<512, 256>>>();
    embw_kernel<<<dim3(16, 128), 256>>>(emb, W, b);

    for (int t = 0; t < TT; t++)
        step_kernel<<<128, 256>>>(tokens, U, t);

    logits_kernel<<<2048, 256>>>(Wd, bd, out);
    softmax_kernel<<<BB * TT, 128>>>(out);
}

// round 3
// speedup vs baseline: 2.0514x; 2.0514x over previous
#include <cuda_runtime.h>
#include <cuda_bf16.h>
#include <cstdint>
#include <math.h>

#define BB 128
#define TT 512
#define VV 128
#define EE 256
#define HH 1024
#define FH 4096   // 4*H

// ======================= static device scratch =======================
__device__ float g_embW[VV * FH];                    // emb@W + b
__device__ float g_h[2][BB * HH];                    // fp32 hidden, double-buffered
__device__ float g_c[BB * HH];                       // cell state
__device__ float g_states[(size_t)BB * TT * HH];     // all h_t (256 MB)
__device__ __nv_bfloat16 g_hbf[2][2][BB * HH];       // [parity][hi/lo] split h
__device__ __nv_bfloat16 g_Ubhi[(size_t)FH * HH];    // U as [n=4j+g][k], hi part
__device__ __nv_bfloat16 g_Ublo[(size_t)FH * HH];    // lo part

// ======================= PTX helpers (sm_100 baseline features only) =======================
__device__ __forceinline__ uint32_t smem_u32(const void* p) {
    uint32_t a;
    asm("{ .reg .u64 t; cvta.to.shared.u64 t, %1; cvt.u32.u64 %0, t; }" : "=r"(a) : "l"(p));
    return a;
}
__device__ __forceinline__ void cp16(uint32_t s, const void* g) {
    asm volatile("cp.async.cg.shared.global [%0], [%1], 16;" :: "r"(s), "l"(g));
}
#define CP_COMMIT() asm volatile("cp.async.commit_group;" ::: "memory")
#define CP_WAIT0()  asm volatile("cp.async.wait_group 0;" ::: "memory")
#define CP_WAIT1()  asm volatile("cp.async.wait_group 1;" ::: "memory")

__device__ __forceinline__ void ldmx4(uint32_t* r, uint32_t addr) {
    asm volatile("ldmatrix.sync.aligned.m8n8.x4.shared.b16 {%0,%1,%2,%3}, [%4];"
        : "=r"(r[0]), "=r"(r[1]), "=r"(r[2]), "=r"(r[3]) : "r"(addr));
}
__device__ __forceinline__ void mma_bf16(float* c, const uint32_t* a, const uint32_t* b) {
    asm volatile(
        "mma.sync.aligned.m16n8k16.row.col.f32.bf16.bf16.f32 "
        "{%0,%1,%2,%3}, {%4,%5,%6,%7}, {%8,%9}, {%0,%1,%2,%3};"
        : "+f"(c[0]), "+f"(c[1]), "+f"(c[2]), "+f"(c[3])
        : "r"(a[0]), "r"(a[1]), "r"(a[2]), "r"(a[3]), "r"(b[0]), "r"(b[1]));
}

// ======================= init =======================
__global__ void zero_hc_kernel() {
    int i = blockIdx.x * blockDim.x + threadIdx.x;   // 131072 total
    g_h[0][i] = 0.0f;
    g_c[i]    = 0.0f;
    g_hbf[0][0][i] = __float2bfloat16(0.0f);
    g_hbf[0][1][i] = __float2bfloat16(0.0f);
}

// U[k][g*H + j]  ->  Ub[n = 4j+g][k], split hi/lo bf16
__global__ void usplit_kernel(const float* __restrict__ U) {
    int idx = blockIdx.x * 256 + threadIdx.x;        // 4M total
    int R = idx >> 10, k = idx & 1023;
    int j = R >> 2, g = R & 3;
    float v = U[(size_t)k * FH + g * HH + j];
    __nv_bfloat16 hi = __float2bfloat16(v);
    g_Ubhi[idx] = hi;
    g_Ublo[idx] = __float2bfloat16(v - __bfloat162float(hi));
}

// embW = emb @ W + b
__global__ void embw_kernel(const float* __restrict__ emb,
                            const float* __restrict__ W,
                            const float* __restrict__ b) {
    __shared__ float se[EE];
    int v   = blockIdx.y;
    int col = blockIdx.x * blockDim.x + threadIdx.x;
    se[threadIdx.x] = emb[v * EE + threadIdx.x];
    __syncthreads();
    float acc = b[col];
#pragma unroll 8
    for (int k = 0; k < EE; k++)
        acc = fmaf(se[k], W[k * FH + col], acc);
    g_embW[v * FH + col] = acc;
}

// ======================= mma.sync LSTM step =======================
// grid = 128 CTAs (CTA bx owns n = bx*32..+31, i.e. j = bx*8..+7), 256 threads (8 warps).
// Warp tile M=32 x N=16; K=1024 in 16 chunks of 64; double-buffered cp.async smem.
// 3 split-bf16 passes per chunk: Ahi*Bhi + Ahi*Blo + Alo*Bhi.
#define SROWB 144                       // 64 bf16 = 128B + 16B pad (ldmatrix conflict-free)
#define OFFA  0                         // A: [buf][sel][128][144B]  = 73728 B
#define OFFB  73728                     // B: [buf][sel][32][144B]   = 18432 B
#define STEP_SMEM 92160

__global__ void __launch_bounds__(256) step_mma(const int* __restrict__ tokens, int t) {
    extern __shared__ char smem[];
    const uint32_t sb  = smem_u32(smem);
    const int tid  = threadIdx.x;
    const int wid  = tid >> 5;
    const int lane = tid & 31;
    const int bx   = blockIdx.x;
    const int par  = t & 1;

    const __nv_bfloat16* __restrict__ Ahi = g_hbf[par][0];
    const __nv_bfloat16* __restrict__ Alo = g_hbf[par][1];

    const int m0w = (wid >> 1) * 32;    // warp M origin
    const int n0w = (wid & 1) * 16;     // warp N origin (within 32)

    float acc[2][2][4];
#pragma unroll
    for (int a = 0; a < 2; a++)
#pragma unroll
        for (int bq = 0; bq < 2; bq++)
#pragma unroll
            for (int r = 0; r < 4; r++) acc[a][bq][r] = 0.0f;

    // ---- chunk loader: 2560 x 16B segs (A hi/lo: 2048, B hi/lo: 512) ----
    auto load_chunk = [&](int c, int buf) {
        const int k0 = c * 64;
#pragma unroll
        for (int it = 0; it < 10; it++) {
            int i = tid + it * 256;
            if (i < 2048) {
                int sel = i >> 10, rs = i & 1023;
                int row = rs >> 3, seg = rs & 7;
                uint32_t dst = sb + OFFA + (uint32_t)((buf * 2 + sel) * 128 + row) * SROWB + seg * 16;
                const __nv_bfloat16* src = (sel ? Alo : Ahi) + row * HH + k0 + seg * 8;
                cp16(dst, src);
            } else {
                int q = i - 2048;
                int sel = q >> 8, rs = q & 255;
                int row = rs >> 3, seg = rs & 7;
                uint32_t dst = sb + OFFB + (uint32_t)((buf * 2 + sel) * 32 + row) * SROWB + seg * 16;
                const __nv_bfloat16* src = (sel ? g_Ublo : g_Ubhi) + (size_t)(bx * 32 + row) * HH + k0 + seg * 8;
                cp16(dst, src);
            }
        }
        CP_COMMIT();
    };

    load_chunk(0, 0);

    for (int c = 0; c < 16; c++) {
        const int buf = c & 1;
        if (c + 1 < 16) { load_chunk(c + 1, (c + 1) & 1); CP_WAIT1(); }
        else            { CP_WAIT0(); }
        __syncthreads();

        const uint32_t baseA = sb + OFFA + (uint32_t)(buf * 2) * 128 * SROWB;
        const uint32_t baseB = sb + OFFB + (uint32_t)(buf * 2) * 32 * SROWB;

#pragma unroll
        for (int kt = 0; kt < 4; kt++) {
            uint32_t ah[2][4], al[2][4], bh[4], bl[4];
            // A fragments: rows m0w + mt*16 + (lane&15), k = kt*16 + (lane>>4)*8
#pragma unroll
            for (int mt = 0; mt < 2; mt++) {
                uint32_t ad = baseA + (uint32_t)(m0w + mt * 16 + (lane & 15)) * SROWB
                                    + (uint32_t)(kt * 16 + (lane >> 4) * 8) * 2;
                ldmx4(ah[mt], ad);
                ldmx4(al[mt], ad + 128 * SROWB);
            }
            // B fragments: rows n0w + (lane>>4)*8 + (lane&7), k = kt*16 + ((lane>>3)&1)*8
            {
                uint32_t bd = baseB + (uint32_t)(n0w + (lane >> 4) * 8 + (lane & 7)) * SROWB
                                    + (uint32_t)(kt * 16 + ((lane >> 3) & 1) * 8) * 2;
                ldmx4(bh, bd);
                ldmx4(bl, bd + 32 * SROWB);
            }
#pragma unroll
            for (int mt = 0; mt < 2; mt++)
#pragma unroll
                for (int nq = 0; nq < 2; nq++) {
                    mma_bf16(acc[mt][nq], ah[mt], bh + nq * 2);   // hi*hi
                    mma_bf16(acc[mt][nq], ah[mt], bl + nq * 2);   // hi*lo
                    mma_bf16(acc[mt][nq], al[mt], bh + nq * 2);   // lo*hi
                }
        }
        __syncthreads();   // all reads of buf done before it is refilled at c+2
    }

    // ---- stage z to smem (aliases A buffers; loop already ended with a sync) ----
    float* z = (float*)smem;            // [128][33]
#pragma unroll
    for (int mt = 0; mt < 2; mt++)
#pragma unroll
        for (int nq = 0; nq < 2; nq++) {
            int r0 = m0w + mt * 16 + (lane >> 2);
            int c0 = n0w + nq * 8 + (lane & 3) * 2;
            z[r0 * 33 + c0]       = acc[mt][nq][0];
            z[r0 * 33 + c0 + 1]   = acc[mt][nq][1];
            z[(r0 + 8) * 33 + c0]     = acc[mt][nq][2];
            z[(r0 + 8) * 33 + c0 + 1] = acc[mt][nq][3];
        }
    __syncthreads();

    // ---- fused gate epilogue: 1024 (m, j) items, 4 per thread ----
    const int m  = tid & 127;
    const int jg = tid >> 7;            // 0..1
    const int tok = tokens[m * TT + t];
    const bool mk = (tok != 0);
    const float* __restrict__ ew    = g_embW + (size_t)tok * FH;
    const float* __restrict__ hprev = g_h[par];
    float* __restrict__ hnext = g_h[par ^ 1];
    __nv_bfloat16* __restrict__ hbh = g_hbf[par ^ 1][0];
    __nv_bfloat16* __restrict__ hbl = g_hbf[par ^ 1][1];

#pragma unroll
    for (int q = 0; q < 4; q++) {
        int jj = jg * 4 + q;            // 0..7
        int j  = bx * 8 + jj;
        float zi = z[m * 33 + 4 * jj + 0] + ew[j];
        float zf = z[m * 33 + 4 * jj + 1] + ew[HH + j];
        float zg = z[m * 33 + 4 * jj + 2] + ew[2 * HH + j];
        float zo = z[m * 33 + 4 * jj + 3] + ew[3 * HH + j];
        float ig = 1.0f / (1.0f + __expf(-zi));
        float fg = 1.0f / (1.0f + __expf(-zf));
        float gg = tanhf(zg);
        float og = 1.0f / (1.0f + __expf(-zo));
        float cp = g_c[m * HH + j];
        float cn = fg * cp + ig * gg;
        float hn = og * tanhf(cn);
        float hp = hprev[m * HH + j];
        float ho = mk ? hn : hp;
        float co = mk ? cn : cp;
        g_c[m * HH + j]   = co;
        hnext[m * HH + j] = ho;
        __nv_bfloat16 hh = __float2bfloat16(ho);
        hbh[m * HH + j] = hh;
        hbl[m * HH + j] = __float2bfloat16(ho - __bfloat162float(hh));
        g_states[((size_t)m * TT + t) * HH + j] = ho;
    }
}

// ======================= logits = states @ Wd + bd =======================
__global__ void __launch_bounds__(256) logits_kernel(const float* __restrict__ Wd,
                                                     const float* __restrict__ bd,
                                                     float* __restrict__ out) {
    __shared__ float Ss[32][33];
    __shared__ float Ws[32][128];

    const int tid = threadIdx.x;
    const int tx  = tid & 31;
    const int ty  = tid >> 5;
    const size_t row0 = (size_t)blockIdx.x * 32;

    float acc[4][4];
#pragma unroll
    for (int i = 0; i < 4; i++)
#pragma unroll
        for (int jn = 0; jn < 4; jn++) acc[i][jn] = 0.0f;

    for (int k0 = 0; k0 < HH; k0 += 32) {
#pragma unroll
        for (int r = 0; r < 4; r++) {
            int idx = tid + r * 256;
            int rr = idx >> 5, kk = idx & 31;
            Ss[rr][kk] = g_states[(row0 + rr) * HH + k0 + kk];
        }
#pragma unroll
        for (int r = 0; r < 16; r++) {
            int idx = tid + r * 256;
            int kk = idx >> 7, v = idx & 127;
            Ws[kk][v] = Wd[(k0 + kk) * VV + v];
        }
        __syncthreads();
#pragma unroll
        for (int kk = 0; kk < 32; kk++) {
            float4 b4 = *reinterpret_cast<const float4*>(&Ws[kk][tx * 4]);
            float a0 = Ss[ty * 4 + 0][kk];
            float a1 = Ss[ty * 4 + 1][kk];
            float a2 = Ss[ty * 4 + 2][kk];
            float a3 = Ss[ty * 4 + 3][kk];
            acc[0][0] = fmaf(a0, b4.x, acc[0][0]);
            acc[0][1] = fmaf(a0, b4.y, acc[0][1]);
            acc[0][2] = fmaf(a0, b4.z, acc[0][2]);
            acc[0][3] = fmaf(a0, b4.w, acc[0][3]);
            acc[1][0] = fmaf(a1, b4.x, acc[1][0]);
            acc[1][1] = fmaf(a1, b4.y, acc[1][1]);
            acc[1][2] = fmaf(a1, b4.z, acc[1][2]);
            acc[1][3] = fmaf(a1, b4.w, acc[1][3]);
            acc[2][0] = fmaf(a2, b4.x, acc[2][0]);
            acc[2][1] = fmaf(a2, b4.y, acc[2][1]);
            acc[2][2] = fmaf(a2, b4.z, acc[2][2]);
            acc[2][3] = fmaf(a2, b4.w, acc[2][3]);
            acc[3][0] = fmaf(a3, b4.x, acc[3][0]);
            acc[3][1] = fmaf(a3, b4.y, acc[3][1]);
            acc[3][2] = fmaf(a3, b4.z, acc[3][2]);
            acc[3][3] = fmaf(a3, b4.w, acc[3][3]);
        }
        __syncthreads();
    }

#pragma unroll
    for (int im = 0; im < 4; im++)
#pragma unroll
        for (int iv = 0; iv < 4; iv++) {
            int v = tx * 4 + iv;
            out[(row0 + ty * 4 + im) * VV + v] = acc[im][iv] + bd[v];
        }
}

// ======================= row softmax (V=128) =======================
__global__ void softmax_kernel(float* __restrict__ out) {
    __shared__ float red[4];
    const size_t row = blockIdx.x;
    const int v    = threadIdx.x;
    const int lane = v & 31;
    const int wid  = v >> 5;

    float x = out[row * VV + v];

    float mval = x;
#pragma unroll
    for (int o = 16; o > 0; o >>= 1)
        mval = fmaxf(mval, __shfl_xor_sync(0xFFFFFFFFu, mval, o));
    if (lane == 0) red[wid] = mval;
    __syncthreads();
    mval = fmaxf(fmaxf(red[0], red[1]), fmaxf(red[2], red[3]));
    __syncthreads();

    float e = expf(x - mval);
    float s = e;
#pragma unroll
    for (int o = 16; o > 0; o >>= 1)
        s += __shfl_xor_sync(0xFFFFFFFFu, s, o);
    if (lane == 0) red[wid] = s;
    __syncthreads();
    s = red[0] + red[1] + red[2] + red[3];

    out[row * VV + v] = e / s;
}

// ======================= launch =======================
extern "C" void kernel_launch(void* const* d_in, const int* in_sizes, int n_in,
                              void* d_out, int out_size) {
    const int*   tokens = (const int*)  d_in[0];
    const float* emb    = (const float*)d_in[1];
    const float* W      = (const float*)d_in[2];
    const float* U      = (const float*)d_in[3];
    const float* b      = (const float*)d_in[4];
    const float* Wd     = (const float*)d_in[5];
    const float* bd     = (const float*)d_in[6];
    float* out = (float*)d_out;

    static bool attr_set = false;
    if (!attr_set) {
        cudaFuncSetAttribute(step_mma, cudaFuncAttributeMaxDynamicSharedMemorySize, STEP_SMEM);
        attr_set = true;
    }

    zero_hc_kernel<<<512, 256>>>();
    usplit_kernel<<<(FH * HH) / 256, 256>>>(U);
    embw_kernel<<<dim3(16, 128), 256>>>(emb, W, b);

    for (int t = 0; t < TT; t++)
        step_mma<<<128, 256, STEP_SMEM>>>(tokens, t);

    logits_kernel<<<2048, 256>>>(Wd, bd, out);
    softmax_kernel<<<BB * TT, 128>>>(out);
}